// round 3
// baseline (speedup 1.0000x reference)
#include <cuda_runtime.h>
#include <math.h>

// ---------------------------------------------------------------------------
// ColorHistogramMatchingLoss
//
// hist[b,c,u,v] = sum_n w[n] * rbf(du[n])[u] * rbf(dv[n])[v]   (D=64 bins)
// Key identities used:
//   * vr - ur = lg - lb, so only 3 distinct rbf vectors per pixel:
//       A = rbf(lr-lg), B = rbf(lr-lb), C = rbf(lg-lb)
//   * rbf(-d) is the exact bin-reversal of rbf(d) (symmetric centers), and
//     the loss is invariant to a consistent per-channel bin permutation
//     (applied identically to x and y). So:
//       c0 = (w*A) x B,  c1 = A x (w*C),  c2 = B x (w*C)
//   * with normalized hists: loss_b = sqrt(1 - Sxy / sqrt(Sx*Sy)) where
//       Sx = sum hx, Sy = sum hy, Sxy = sum sqrt(hx*hy)   (unnormalized)
//
// Main kernel: per block = (tensor, batch, pixel-slice). 192 threads =
// 3 groups of 64; each group accumulates one channel's 64x64 histogram in
// registers (8x8 tile/thread, packed as f32x2 pairs along v, accumulated
// with fma.rn.f32x2 = FFMA2, 2x fp32 FMA per instruction on sm_103a).
// ---------------------------------------------------------------------------

#define D_HIST 64
#define PX 16                    // pixels per smem tile
#define SLICES 64
#define NPIX 65536
#define PIX_PER_SLICE (NPIX / SLICES)   // 1024
#define TILES (PIX_PER_SLICE / PX)      // 64
#define HIST_ELEMS (2 * 8 * 3 * D_HIST * D_HIST)

__device__ float g_hist[HIST_ELEMS];

typedef unsigned long long ull;

__device__ __forceinline__ ull ffma2(ull a, ull b, ull c) {
#if __CUDA_ARCH__ >= 1000
    ull d;
    asm("fma.rn.f32x2 %0, %1, %2, %3;" : "=l"(d) : "l"(a), "l"(b), "l"(c));
    return d;
#else
    float2 af, bf, cf;
    asm("mov.b64 {%0, %1}, %2;" : "=f"(af.x), "=f"(af.y) : "l"(a));
    asm("mov.b64 {%0, %1}, %2;" : "=f"(bf.x), "=f"(bf.y) : "l"(b));
    asm("mov.b64 {%0, %1}, %2;" : "=f"(cf.x), "=f"(cf.y) : "l"(c));
    cf.x = fmaf(af.x, bf.x, cf.x);
    cf.y = fmaf(af.y, bf.y, cf.y);
    ull d;
    asm("mov.b64 %0, {%1, %2};" : "=l"(d) : "f"(cf.x), "f"(cf.y));
    return d;
#endif
}

__device__ __forceinline__ ull dup2(float v) {
    ull r;
    asm("mov.b64 %0, {%1, %1};" : "=l"(r) : "f"(v));
    return r;
}

__device__ __forceinline__ float2 unpack2(ull p) {
    float2 r;
    asm("mov.b64 {%0, %1}, %2;" : "=f"(r.x), "=f"(r.y) : "l"(p));
    return r;
}

__global__ __launch_bounds__(192, 2)
void hist_kernel(const float* __restrict__ x, const float* __restrict__ y) {
    // Dup arrays (u-side operands, each value stored as {v,v} f32x2), padded
    // index u -> u + (u>>2) for bank-conflict-free LDS.64 across tu groups.
    // sUA[0]=w*A (c0-u), sUA[1]=A (c1-u), sUA[2]=B (c2-u)
    __shared__ __align__(16) ull sUA[3][PX][80];
    // Plain arrays (v-side), padded index v -> v + (v>>3)*4, conflict-free
    // float4 loads. sV[0]=B (c0-v), sV[1]=w*C (c1,c2-v)
    __shared__ __align__(16) float sV[2][PX][96];
    __shared__ float sD[3][PX];
    __shared__ float sW[PX];

    const int tid = threadIdx.x;
    const int bid = blockIdx.x;
    const int slice = bid & (SLICES - 1);
    const int batch = (bid >> 6) & 7;
    const int tensor = bid >> 9;

    const float* img = tensor ? y : x;
    const float* cr = img + batch * 3 * NPIX;
    const float* cg = cr + NPIX;
    const float* cb = cg + NPIX;
    const int base_n = slice * PIX_PER_SLICE;

    // producer identity: vec 0 -> A, 1 -> B, 2 -> C; element e in [0,64)
    const int vec = tid >> 6;
    const int e = tid & 63;
    const int di = e + (e >> 2);              // dup-array padded index
    const int pi = e + ((e >> 3) << 2);       // plain-array padded index
    const float ck50 = (-3.0f + (float)e * (6.0f / 63.0f)) * 50.0f;

    // consumer identity: group = channel, 8x8 tile at (tu*8, tv*8)
    const int grp = tid >> 6;
    const int tu = (tid & 63) >> 3;
    const int tv = tid & 7;

    ull acc[8][4];
#pragma unroll
    for (int i = 0; i < 8; ++i)
#pragma unroll
        for (int j = 0; j < 4; ++j) acc[i][j] = 0ull;

    // prefetch first pixel tile
    float pr = 0.f, pg = 0.f, pb = 0.f;
    if (tid < PX) {
        int n = base_n + tid;
        pr = cr[n]; pg = cg[n]; pb = cb[n];
    }

    const ull* ubase = &sUA[grp][0][0] + tu * 10;
    const float* vbase = &sV[grp == 0 ? 0 : 1][0][0] + tv * 12;

    for (int tile = 0; tile < TILES; ++tile) {
        // ---- Phase A: pixel scalars (16 threads) + prefetch next tile ----
        if (tid < PX) {
            float r = pr + 1e-6f, g = pg + 1e-6f, b = pb + 1e-6f;
            sW[tid] = sqrtf(fmaf(r, r, fmaf(g, g, b * b)));
            float lr = logf(r), lg = logf(g), lb = logf(b);
            sD[0][tid] = lr - lg;   // A: ur
            sD[1][tid] = lr - lb;   // B: vr
            sD[2][tid] = lg - lb;   // C: vr - ur
            if (tile + 1 < TILES) {
                int n = base_n + (tile + 1) * PX + tid;
                pr = cr[n]; pg = cg[n]; pb = cb[n];
            }
        }
        __syncthreads();

        // ---- Phase B: rbf production (1 element x PX pixels per thread) ----
#pragma unroll
        for (int p = 0; p < PX; ++p) {
            float t = fmaf(sD[vec][p], 50.0f, -ck50);
            float val = __fdividef(1.0f, fmaf(t, t, 1.0f));
            float wv = val * sW[p];
            if (vec == 0) {
                sUA[1][p][di] = dup2(val);   // A   -> c1 u
                sUA[0][p][di] = dup2(wv);    // w*A -> c0 u
            } else if (vec == 1) {
                sUA[2][p][di] = dup2(val);   // B   -> c2 u
                sV[0][p][pi] = val;          // B   -> c0 v
            } else {
                sV[1][p][pi] = wv;           // w*C -> c1,c2 v
            }
        }
        __syncthreads();

        // ---- Phase C: register-tiled outer-product accumulate ----
#pragma unroll 4
        for (int p = 0; p < PX; ++p) {
            const ull* up = ubase + p * 80;
            const float* vp = vbase + p * 96;
            ull av[8];
#pragma unroll
            for (int i = 0; i < 8; ++i) av[i] = up[i + (i >> 2)];
            ulonglong2 q0 = *reinterpret_cast<const ulonglong2*>(vp);
            ulonglong2 q1 = *reinterpret_cast<const ulonglong2*>(vp + 4);
            ull bv[4] = {q0.x, q0.y, q1.x, q1.y};
#pragma unroll
            for (int i = 0; i < 8; ++i)
#pragma unroll
                for (int j = 0; j < 4; ++j)
                    acc[i][j] = ffma2(av[i], bv[j], acc[i][j]);
        }
        __syncthreads();
    }

    // ---- Epilogue: flush register tile to global histogram ----
    float* hist = g_hist + ((tensor * 8 + batch) * 3 + grp) * (D_HIST * D_HIST);
#pragma unroll
    for (int i = 0; i < 8; ++i) {
#pragma unroll
        for (int j = 0; j < 4; ++j) {
            float2 v = unpack2(acc[i][j]);
            int u = tu * 8 + i;
            int vv = tv * 8 + 2 * j;
            atomicAdd(&hist[u * D_HIST + vv], v.x);
            atomicAdd(&hist[u * D_HIST + vv + 1], v.y);
        }
    }
}

__global__ void zero_kernel(float* out) {
    int i = blockIdx.x * blockDim.x + threadIdx.x;
    if (i < HIST_ELEMS) g_hist[i] = 0.0f;
    if (i == 0) out[0] = 0.0f;
}

// loss_b = sqrt(max(0, 1 - Sxy / sqrt(Sx * Sy))); out = mean over b
__global__ void finalize_kernel(float* out) {
    const int b = blockIdx.x;
    const int tid = threadIdx.x;
    const int n = 3 * D_HIST * D_HIST;
    const float* hx = g_hist + b * n;
    const float* hy = g_hist + 8 * n + b * n;
    float sx = 0.f, sy = 0.f, sxy = 0.f;
    for (int i = tid; i < n; i += blockDim.x) {
        float a = hx[i], c = hy[i];
        sx += a; sy += c; sxy += sqrtf(a * c);
    }
#pragma unroll
    for (int off = 16; off; off >>= 1) {
        sx += __shfl_xor_sync(0xFFFFFFFFu, sx, off);
        sy += __shfl_xor_sync(0xFFFFFFFFu, sy, off);
        sxy += __shfl_xor_sync(0xFFFFFFFFu, sxy, off);
    }
    __shared__ float red[3][8];
    int w = tid >> 5, l = tid & 31;
    if (l == 0) { red[0][w] = sx; red[1][w] = sy; red[2][w] = sxy; }
    __syncthreads();
    if (tid == 0) {
        sx = 0.f; sy = 0.f; sxy = 0.f;
        for (int k = 0; k < 8; ++k) {
            sx += red[0][k]; sy += red[1][k]; sxy += red[2][k];
        }
        float s = sxy / sqrtf(sx * sy);
        float h = sqrtf(fmaxf(1.0f - s, 0.0f));
        atomicAdd(out, h * 0.125f);
    }
}

extern "C" void kernel_launch(void* const* d_in, const int* in_sizes, int n_in,
                              void* d_out, int out_size) {
    (void)in_sizes; (void)n_in; (void)out_size;
    const float* x = (const float*)d_in[0];
    const float* y = (const float*)d_in[1];
    float* out = (float*)d_out;

    zero_kernel<<<(HIST_ELEMS + 511) / 512, 512>>>(out);
    hist_kernel<<<2 * 8 * SLICES, 192>>>(x, y);
    finalize_kernel<<<8, 256>>>(out);
}